// round 1
// baseline (speedup 1.0000x reference)
#include <cuda_runtime.h>
#include <cuda_bf16.h>
#include <math.h>

// Problem constants (fixed by the dataset)
#define BATCH   8
#define SEQ     4096
#define HID     768
#define LINES   256
#define ATTH    1024
#define MTOK    (BATCH*SEQ)          // 32768 tokens
#define NPART   16                   // N-dim split of the score GEMM (1024/64)

// Scratch (static device globals — no runtime allocation)
__device__ float g_part[MTOK * NPART];   // per-token partial score sums (deterministic order)
__device__ float g_scores[MTOK];         // final attention scores

// ---------------------------------------------------------------------------
// Kernel 1: tiled SGEMM  C = X[32768,768] @ W1[768,1024], fused +b1, tanh,
// and dot with W2 over this block's 64-column slice. Writes one partial per
// (token, n-tile) so the final sum order is fixed (determinism).
// Block tile 64x64, K-tile 16, 256 threads, 4x4 register tile per thread.
// ---------------------------------------------------------------------------
__global__ __launch_bounds__(256) void score_gemm_kernel(
    const float* __restrict__ X,
    const float* __restrict__ W1,
    const float* __restrict__ b1,
    const float* __restrict__ W2)
{
    const int BM = 64, BN = 64, BK = 16;
    __shared__ float As[16][68];   // [k][m] padded
    __shared__ float Bs[16][64];   // [k][n]
    __shared__ float red[64][17];  // epilogue reduction

    const int bm = blockIdx.x;        // 512 tiles of 64 tokens
    const int bn = blockIdx.y;        // 16 tiles of 64 hidden cols
    const int tid = threadIdx.x;
    const int tx = tid & 15;          // 16 col groups
    const int ty = tid >> 4;          // 16 row groups

    const float* Xb = X  + (size_t)bm * BM * HID;
    const float* Wb = W1 + bn * BN;

    // loader coords
    const int a_k = tid & 15;         // k within tile
    const int a_m = tid >> 4;         // row base (4 rows, stride 16)
    const int b_n = tid & 63;
    const int b_k = tid >> 6;         // k base (4 ks, stride 4)

    float acc[4][4];
#pragma unroll
    for (int i = 0; i < 4; i++)
#pragma unroll
        for (int j = 0; j < 4; j++) acc[i][j] = 0.f;

    for (int k0 = 0; k0 < HID; k0 += BK) {
#pragma unroll
        for (int r = 0; r < 4; r++)
            As[a_k][a_m + 16 * r] = Xb[(size_t)(a_m + 16 * r) * HID + k0 + a_k];
#pragma unroll
        for (int r = 0; r < 4; r++)
            Bs[b_k + 4 * r][b_n] = Wb[(size_t)(k0 + b_k + 4 * r) * ATTH + b_n];
        __syncthreads();

#pragma unroll
        for (int kk = 0; kk < BK; kk++) {
            float a0 = As[kk][ty * 4 + 0];
            float a1 = As[kk][ty * 4 + 1];
            float a2 = As[kk][ty * 4 + 2];
            float a3 = As[kk][ty * 4 + 3];
            float c0 = Bs[kk][tx * 4 + 0];
            float c1 = Bs[kk][tx * 4 + 1];
            float c2 = Bs[kk][tx * 4 + 2];
            float c3 = Bs[kk][tx * 4 + 3];
            acc[0][0] += a0 * c0; acc[0][1] += a0 * c1; acc[0][2] += a0 * c2; acc[0][3] += a0 * c3;
            acc[1][0] += a1 * c0; acc[1][1] += a1 * c1; acc[1][2] += a1 * c2; acc[1][3] += a1 * c3;
            acc[2][0] += a2 * c0; acc[2][1] += a2 * c1; acc[2][2] += a2 * c2; acc[2][3] += a2 * c3;
            acc[3][0] += a3 * c0; acc[3][1] += a3 * c1; acc[3][2] += a3 * c2; acc[3][3] += a3 * c3;
        }
        __syncthreads();
    }

    // Epilogue: +b1, tanh, * W2, sum over the 4 cols this thread owns
    float p[4];
#pragma unroll
    for (int i = 0; i < 4; i++) {
        float s = 0.f;
#pragma unroll
        for (int j = 0; j < 4; j++) {
            int n = bn * BN + tx * 4 + j;
            float h = tanhf(acc[i][j] + b1[n]);
            s += h * W2[n];
        }
        p[i] = s;
    }
#pragma unroll
    for (int i = 0; i < 4; i++) red[ty * 4 + i][tx] = p[i];
    __syncthreads();

    if (tid < 64) {
        float s = 0.f;
#pragma unroll
        for (int j = 0; j < 16; j++) s += red[tid][j];
        g_part[(size_t)(bm * BM + tid) * NPART + bn] = s;
    }
}

// ---------------------------------------------------------------------------
// Kernel 2: deterministic reduce of partials + b2 -> scores
// ---------------------------------------------------------------------------
__global__ void finalize_scores_kernel(const float* __restrict__ b2)
{
    int m = blockIdx.x * blockDim.x + threadIdx.x;
    if (m >= MTOK) return;
    const float4* p = reinterpret_cast<const float4*>(&g_part[(size_t)m * NPART]);
    float4 v0 = p[0], v1 = p[1], v2 = p[2], v3 = p[3];
    float s = ((v0.x + v0.y) + (v0.z + v0.w))
            + ((v1.x + v1.y) + (v1.z + v1.w))
            + ((v2.x + v2.y) + (v2.z + v2.w))
            + ((v3.x + v3.y) + (v3.z + v3.w));
    g_scores[m] = s + b2[0];
}

// ---------------------------------------------------------------------------
// Kernel 3: per-(batch,line) segment softmax + weighted token sum.
// One block per segment; fully deterministic (prefix-scan compaction).
// ---------------------------------------------------------------------------
__global__ __launch_bounds__(256) void aggregate_kernel(
    const float* __restrict__ X,
    const int*   __restrict__ line_ids,
    float* __restrict__ out_feats,
    float* __restrict__ out_mask,   // may be null
    int write_mask)
{
    const int l = blockIdx.x;
    const int b = blockIdx.y;
    const int tid = threadIdx.x;
    const int base = b * SEQ;
    const size_t orow = (size_t)(b * LINES + l) * HID;

    __shared__ float smax[256];
    __shared__ float ssum[256];
    __shared__ int   scnt[256];
    __shared__ int   idxs[SEQ];
    __shared__ float wts[SEQ];
    __shared__ float sm_bcast;
    __shared__ float sdenom;

    // pass 1: segment max
    float m = -INFINITY;
    for (int s = tid; s < SEQ; s += 256)
        if (line_ids[base + s] == l) m = fmaxf(m, g_scores[base + s]);
    smax[tid] = m;
    __syncthreads();
#pragma unroll
    for (int off = 128; off > 0; off >>= 1) {
        if (tid < off) smax[tid] = fmaxf(smax[tid], smax[tid + off]);
        __syncthreads();
    }
    if (tid == 0) sm_bcast = smax[0];
    __syncthreads();
    m = sm_bcast;

    if (m < -1e37f) {  // empty segment
        for (int c = tid; c < HID; c += 256) out_feats[orow + c] = 0.f;
        if (tid == 0 && write_mask) out_mask[b * LINES + l] = 0.f;
        return;
    }

    // pass 2: local exp-sum and match count
    float lsum = 0.f;
    int lcnt = 0;
    for (int s = tid; s < SEQ; s += 256) {
        if (line_ids[base + s] == l) {
            lsum += __expf(g_scores[base + s] - m) ;
            lcnt++;
        }
    }
    // exact exp for accuracy
    lsum = 0.f;
    for (int s = tid; s < SEQ; s += 256)
        if (line_ids[base + s] == l) lsum += expf(g_scores[base + s] - m);

    ssum[tid] = lsum;
    scnt[tid] = lcnt;
    __syncthreads();
#pragma unroll
    for (int off = 128; off > 0; off >>= 1) {
        if (tid < off) ssum[tid] += ssum[tid + off];
        __syncthreads();
    }
    if (tid == 0) sdenom = fmaxf(ssum[0], 1e-20f);
    __syncthreads();
    const float denom = sdenom;

    // inclusive prefix scan of counts (Hillis-Steele)
    for (int off = 1; off < 256; off <<= 1) {
        int v = scnt[tid];
        int add = (tid >= off) ? scnt[tid - off] : 0;
        __syncthreads();
        scnt[tid] = v + add;
        __syncthreads();
    }
    const int cnt = scnt[255];
    int o = scnt[tid] - lcnt;   // exclusive offset

    // pass 3: deterministic compaction
    for (int s = tid; s < SEQ; s += 256) {
        if (line_ids[base + s] == l) {
            idxs[o] = s;
            wts[o]  = expf(g_scores[base + s] - m) / denom;
            o++;
        }
    }
    __syncthreads();

    // pass 4: weighted sum over matched tokens (coalesced per token row)
    float a0 = 0.f, a1 = 0.f, a2 = 0.f;
    const float* Xb = X + (size_t)base * HID;
    for (int t = 0; t < cnt; t++) {
        const float* row = Xb + (size_t)idxs[t] * HID;
        float w = wts[t];
        a0 += w * row[tid];
        a1 += w * row[tid + 256];
        a2 += w * row[tid + 512];
    }
    out_feats[orow + tid]       = a0;
    out_feats[orow + tid + 256] = a1;
    out_feats[orow + tid + 512] = a2;

    if (tid == 0 && write_mask) out_mask[b * LINES + l] = 1.0f;
}

// ---------------------------------------------------------------------------
extern "C" void kernel_launch(void* const* d_in, const int* in_sizes, int n_in,
                              void* d_out, int out_size)
{
    const float* token_hidden = (const float*)d_in[0];
    const int*   line_ids     = (const int*)  d_in[1];
    const float* W1           = (const float*)d_in[2];
    const float* b1           = (const float*)d_in[3];
    const float* W2           = (const float*)d_in[4];
    const float* b2           = (const float*)d_in[5];

    float* out = (float*)d_out;
    const int feat_elems = BATCH * LINES * HID;      // 1,572,864
    const int mask_elems = BATCH * LINES;            // 2,048
    int write_mask = (out_size >= feat_elems + mask_elems) ? 1 : 0;
    float* mask_out = write_mask ? (out + feat_elems) : nullptr;

    dim3 g1(MTOK / 64, ATTH / 64);   // (512, 16)
    score_gemm_kernel<<<g1, 256>>>(token_hidden, W1, b1, W2);

    finalize_scores_kernel<<<MTOK / 256, 256>>>(b2);

    dim3 g2(LINES, BATCH);           // (256, 8)
    aggregate_kernel<<<g2, 256>>>(token_hidden, line_ids, out, mask_out, write_mask);
}

// round 2
// speedup vs baseline: 1.4593x; 1.4593x over previous
#include <cuda_runtime.h>
#include <cuda_bf16.h>
#include <math.h>

// Problem constants (fixed by the dataset)
#define BATCH   8
#define SEQ     4096
#define HID     768
#define LINES   256
#define ATTH    1024
#define MTOK    (BATCH*SEQ)          // 32768 tokens
#define NPART   8                    // N-dim split of the score GEMM (1024/128)

// Scratch (static device globals — no runtime allocation)
__device__ float g_part[MTOK * NPART];   // per-token partial score sums (deterministic order)
__device__ float g_scores[MTOK];         // final attention scores

__device__ __forceinline__ float tanh_hw(float x) {
    float y;
    asm("tanh.approx.f32 %0, %1;" : "=f"(y) : "f"(x));
    return y;
}

// ---------------------------------------------------------------------------
// Kernel 1: 128x128 tiled SGEMM with packed fma.rn.f32x2.
// C = X[32768,768] @ W1[768,1024], fused +b1, tanh, dot with W2 over this
// block's 128-column slice -> one deterministic partial per (token, n-tile).
// 256 threads, 8x8 register tile per thread (stored as 8x4 f32x2 pairs).
// ---------------------------------------------------------------------------
#define BM 128
#define BN 128
#define BK 16

__global__ __launch_bounds__(256) void score_gemm_kernel(
    const float* __restrict__ X,
    const float* __restrict__ W1,
    const float* __restrict__ b1,
    const float* __restrict__ W2)
{
    __shared__ float As[BK][BM + 4];   // [k][m], row = 132 floats (16B-aligned rows)
    __shared__ float Bs[BK][BN];       // [k][n]
    __shared__ float red[BM][17];      // epilogue cross-thread reduction

    const int bm  = blockIdx.x;        // 256 tiles of 128 tokens
    const int bn  = blockIdx.y;        // 8 tiles of 128 hidden cols
    const int tid = threadIdx.x;
    const int tx  = tid & 15;          // 16 col groups (8 cols each)
    const int ty  = tid >> 4;          // 16 row groups (8 rows each)

    const float* Xb = X  + (size_t)bm * BM * HID;
    const float* Wb = W1 + (size_t)bn * BN;

    // A loader: 512 float4 per tile -> 2 per thread. id -> (row, k-quad)
    // row = id/4 (0..127), kq = (id%4)*4
    // B loader: 512 float4 per tile -> 2 per thread. id -> (krow, ncol)
    // krow = id/32 (0..15), nc = (id%32)*4

    unsigned long long acc[8][4];
#pragma unroll
    for (int i = 0; i < 8; i++)
#pragma unroll
        for (int j = 0; j < 4; j++) acc[i][j] = 0ULL;

    float4 pa[2], pb[2];

    // prologue: load tile 0
#pragma unroll
    for (int r = 0; r < 2; r++) {
        int id  = tid + 256 * r;
        int row = id >> 2, kq = (id & 3) * 4;
        pa[r] = *reinterpret_cast<const float4*>(&Xb[(size_t)row * HID + kq]);
        int kr = id >> 5, nc = (id & 31) * 4;
        pb[r] = *reinterpret_cast<const float4*>(&Wb[(size_t)kr * ATTH + nc]);
    }

    const int NKT = HID / BK;   // 48
    for (int kt = 0; kt < NKT; kt++) {
        // store staged tile to smem
#pragma unroll
        for (int r = 0; r < 2; r++) {
            int id  = tid + 256 * r;
            int row = id >> 2, kq = (id & 3) * 4;
            As[kq + 0][row] = pa[r].x;
            As[kq + 1][row] = pa[r].y;
            As[kq + 2][row] = pa[r].z;
            As[kq + 3][row] = pa[r].w;
            int kr = id >> 5, nc = (id & 31) * 4;
            *reinterpret_cast<float4*>(&Bs[kr][nc]) = pb[r];
        }
        __syncthreads();

        // prefetch next tile into registers
        if (kt + 1 < NKT) {
            int k0 = (kt + 1) * BK;
#pragma unroll
            for (int r = 0; r < 2; r++) {
                int id  = tid + 256 * r;
                int row = id >> 2, kq = (id & 3) * 4;
                pa[r] = *reinterpret_cast<const float4*>(&Xb[(size_t)row * HID + k0 + kq]);
                int kr = id >> 5, nc = (id & 31) * 4;
                pb[r] = *reinterpret_cast<const float4*>(&Wb[(size_t)(k0 + kr) * ATTH + nc]);
            }
        }

#pragma unroll
        for (int kk = 0; kk < BK; kk++) {
            // A fragment: 8 rows (broadcast within warp)
            float4 a0 = *reinterpret_cast<const float4*>(&As[kk][ty * 8]);
            float4 a1 = *reinterpret_cast<const float4*>(&As[kk][ty * 8 + 4]);
            float av[8] = {a0.x, a0.y, a0.z, a0.w, a1.x, a1.y, a1.z, a1.w};
            // B fragment: 8 cols as 4 f32x2 pairs
            ulonglong2 bv0 = *reinterpret_cast<const ulonglong2*>(&Bs[kk][tx * 8]);
            ulonglong2 bv1 = *reinterpret_cast<const ulonglong2*>(&Bs[kk][tx * 8 + 4]);
            unsigned long long bp[4] = {bv0.x, bv0.y, bv1.x, bv1.y};
#pragma unroll
            for (int i = 0; i < 8; i++) {
                unsigned long long ap;
                asm("mov.b64 %0, {%1, %1};" : "=l"(ap) : "f"(av[i]));
#pragma unroll
                for (int j = 0; j < 4; j++) {
                    asm("fma.rn.f32x2 %0, %1, %2, %0;" : "+l"(acc[i][j]) : "l"(ap), "l"(bp[j]));
                }
            }
        }
        __syncthreads();
    }

    // Epilogue: +b1, tanh (HW), * W2, sum over the 8 cols this thread owns
    float bb[8], ww[8];
#pragma unroll
    for (int j = 0; j < 8; j++) {
        int n = bn * BN + tx * 8 + j;
        bb[j] = b1[n];
        ww[j] = W2[n];
    }
#pragma unroll
    for (int i = 0; i < 8; i++) {
        float s = 0.f;
#pragma unroll
        for (int j = 0; j < 4; j++) {
            float lo, hi;
            asm("mov.b64 {%0, %1}, %2;" : "=f"(lo), "=f"(hi) : "l"(acc[i][j]));
            s += tanh_hw(lo + bb[2 * j])     * ww[2 * j];
            s += tanh_hw(hi + bb[2 * j + 1]) * ww[2 * j + 1];
        }
        red[ty * 8 + i][tx] = s;
    }
    __syncthreads();

    if (tid < BM) {
        float s = 0.f;
#pragma unroll
        for (int j = 0; j < 16; j++) s += red[tid][j];
        g_part[(size_t)(bm * BM + tid) * NPART + bn] = s;
    }
}

// ---------------------------------------------------------------------------
// Kernel 2: deterministic reduce of partials + b2 -> scores
// ---------------------------------------------------------------------------
__global__ void finalize_scores_kernel(const float* __restrict__ b2)
{
    int m = blockIdx.x * blockDim.x + threadIdx.x;
    if (m >= MTOK) return;
    const float4* p = reinterpret_cast<const float4*>(&g_part[(size_t)m * NPART]);
    float4 v0 = p[0], v1 = p[1];
    float s = ((v0.x + v0.y) + (v0.z + v0.w))
            + ((v1.x + v1.y) + (v1.z + v1.w));
    g_scores[m] = s + b2[0];
}

// ---------------------------------------------------------------------------
// Kernel 3: per-(batch,line) segment softmax + weighted token sum.
// One block per segment; fully deterministic (prefix-scan compaction).
// ---------------------------------------------------------------------------
__global__ __launch_bounds__(256) void aggregate_kernel(
    const float* __restrict__ X,
    const int*   __restrict__ line_ids,
    float* __restrict__ out_feats,
    float* __restrict__ out_mask,   // may be null
    int write_mask)
{
    const int l = blockIdx.x;
    const int b = blockIdx.y;
    const int tid = threadIdx.x;
    const int base = b * SEQ;
    const size_t orow = (size_t)(b * LINES + l) * HID;

    __shared__ float smax[256];
    __shared__ float ssum[256];
    __shared__ int   scnt[256];
    __shared__ int   idxs[SEQ];
    __shared__ float wts[SEQ];
    __shared__ float sm_bcast;
    __shared__ float sdenom;

    // pass 1: segment max
    float m = -INFINITY;
    for (int s = tid; s < SEQ; s += 256)
        if (line_ids[base + s] == l) m = fmaxf(m, g_scores[base + s]);
    smax[tid] = m;
    __syncthreads();
#pragma unroll
    for (int off = 128; off > 0; off >>= 1) {
        if (tid < off) smax[tid] = fmaxf(smax[tid], smax[tid + off]);
        __syncthreads();
    }
    if (tid == 0) sm_bcast = smax[0];
    __syncthreads();
    m = sm_bcast;

    if (m < -1e37f) {  // empty segment
        for (int c = tid; c < HID; c += 256) out_feats[orow + c] = 0.f;
        if (tid == 0 && write_mask) out_mask[b * LINES + l] = 0.f;
        return;
    }

    // pass 2: local exp-sum and match count
    float lsum = 0.f;
    int lcnt = 0;
    for (int s = tid; s < SEQ; s += 256) {
        if (line_ids[base + s] == l) {
            lsum += expf(g_scores[base + s] - m);
            lcnt++;
        }
    }
    ssum[tid] = lsum;
    scnt[tid] = lcnt;
    __syncthreads();
#pragma unroll
    for (int off = 128; off > 0; off >>= 1) {
        if (tid < off) ssum[tid] += ssum[tid + off];
        __syncthreads();
    }
    if (tid == 0) sdenom = fmaxf(ssum[0], 1e-20f);
    __syncthreads();
    const float denom = sdenom;

    // inclusive prefix scan of counts (Hillis-Steele)
    for (int off = 1; off < 256; off <<= 1) {
        int v = scnt[tid];
        int add = (tid >= off) ? scnt[tid - off] : 0;
        __syncthreads();
        scnt[tid] = v + add;
        __syncthreads();
    }
    const int cnt = scnt[255];
    int o = scnt[tid] - lcnt;   // exclusive offset

    // pass 3: deterministic compaction
    for (int s = tid; s < SEQ; s += 256) {
        if (line_ids[base + s] == l) {
            idxs[o] = s;
            wts[o]  = expf(g_scores[base + s] - m) / denom;
            o++;
        }
    }
    __syncthreads();

    // pass 4: weighted sum over matched tokens (coalesced per token row)
    float a0 = 0.f, a1 = 0.f, a2 = 0.f;
    const float* Xb = X + (size_t)base * HID;
    for (int t = 0; t < cnt; t++) {
        const float* row = Xb + (size_t)idxs[t] * HID;
        float w = wts[t];
        a0 += w * row[tid];
        a1 += w * row[tid + 256];
        a2 += w * row[tid + 512];
    }
    out_feats[orow + tid]       = a0;
    out_feats[orow + tid + 256] = a1;
    out_feats[orow + tid + 512] = a2;

    if (tid == 0 && write_mask) out_mask[b * LINES + l] = 1.0f;
}

// ---------------------------------------------------------------------------
extern "C" void kernel_launch(void* const* d_in, const int* in_sizes, int n_in,
                              void* d_out, int out_size)
{
    const float* token_hidden = (const float*)d_in[0];
    const int*   line_ids     = (const int*)  d_in[1];
    const float* W1           = (const float*)d_in[2];
    const float* b1           = (const float*)d_in[3];
    const float* W2           = (const float*)d_in[4];
    const float* b2           = (const float*)d_in[5];

    float* out = (float*)d_out;
    const int feat_elems = BATCH * LINES * HID;      // 1,572,864
    const int mask_elems = BATCH * LINES;            // 2,048
    int write_mask = (out_size >= feat_elems + mask_elems) ? 1 : 0;
    float* mask_out = write_mask ? (out + feat_elems) : nullptr;

    dim3 g1(MTOK / BM, ATTH / BN);   // (256, 8)
    score_gemm_kernel<<<g1, 256>>>(token_hidden, W1, b1, W2);

    finalize_scores_kernel<<<MTOK / 256, 256>>>(b2);

    dim3 g2(LINES, BATCH);           // (256, 8)
    aggregate_kernel<<<g2, 256>>>(token_hidden, line_ids, out, mask_out, write_mask);
}

// round 4
// speedup vs baseline: 4.2063x; 2.8824x over previous
#include <cuda_runtime.h>
#include <cuda_bf16.h>
#include <math.h>
#include <stdint.h>

// Problem constants
#define BATCH   8
#define SEQ     4096
#define HID     768
#define LINES   256
#define ATTH    1024
#define MTOK    (BATCH*SEQ)      // 32768
#define NPART   8                // 8 N-tiles of 128

#define BM 128
#define BN 128
#define BK 64
#define NKT (HID/BK)             // 12

// ---- scratch (static device globals) ----
__device__ __nv_bfloat16 g_Xhi[(size_t)MTOK * HID];
__device__ __nv_bfloat16 g_Xlo[(size_t)MTOK * HID];
__device__ __nv_bfloat16 g_Wt [(size_t)ATTH * HID];   // W1^T [N][K]
__device__ float g_part[MTOK * NPART];
__device__ float g_scores[MTOK];

__device__ __forceinline__ float tanh_hw(float x) {
    float y; asm("tanh.approx.f32 %0, %1;" : "=f"(y) : "f"(x)); return y;
}
__device__ __forceinline__ uint32_t smem_u32(const void* p) {
    uint32_t a;
    asm("{ .reg .u64 t; cvta.to.shared.u64 t, %1; cvt.u32.u64 %0, t; }" : "=r"(a) : "l"(p));
    return a;
}
__device__ __forceinline__ void cp16(uint32_t dst, const void* src) {
    asm volatile("cp.async.cg.shared.global [%0], [%1], 16;" :: "r"(dst), "l"(src) : "memory");
}
#define CP_COMMIT()  asm volatile("cp.async.commit_group;" ::: "memory")
#define CP_WAIT(n)   asm volatile("cp.async.wait_group %0;" :: "n"(n) : "memory")

__device__ __forceinline__ void ldm_x4(uint32_t* r, uint32_t addr) {
    asm volatile("ldmatrix.sync.aligned.m8n8.x4.shared.b16 {%0,%1,%2,%3}, [%4];"
                 : "=r"(r[0]), "=r"(r[1]), "=r"(r[2]), "=r"(r[3]) : "r"(addr));
}
__device__ __forceinline__ void mma_bf16(float* c, const uint32_t* a, uint32_t b0, uint32_t b1) {
    asm volatile("mma.sync.aligned.m16n8k16.row.col.f32.bf16.bf16.f32 "
                 "{%0,%1,%2,%3}, {%4,%5,%6,%7}, {%8,%9}, {%0,%1,%2,%3};"
                 : "+f"(c[0]), "+f"(c[1]), "+f"(c[2]), "+f"(c[3])
                 : "r"(a[0]), "r"(a[1]), "r"(a[2]), "r"(a[3]), "r"(b0), "r"(b1));
}

// ---------------------------------------------------------------------------
// Conversion: X fp32 -> hi/lo bf16 planes (row-major)
// ---------------------------------------------------------------------------
__global__ __launch_bounds__(256) void convert_X(const float* __restrict__ X)
{
    size_t i4 = (size_t)blockIdx.x * 256 + threadIdx.x;   // float4 index
    float4 v = reinterpret_cast<const float4*>(X)[i4];
    float xs[4] = {v.x, v.y, v.z, v.w};
    __nv_bfloat16 h[4], l[4];
#pragma unroll
    for (int i = 0; i < 4; i++) {
        h[i] = __float2bfloat16_rn(xs[i]);
        l[i] = __float2bfloat16_rn(xs[i] - __bfloat162float(h[i]));
    }
    reinterpret_cast<uint2*>(g_Xhi)[i4] = *reinterpret_cast<uint2*>(h);
    reinterpret_cast<uint2*>(g_Xlo)[i4] = *reinterpret_cast<uint2*>(l);
}

// Conversion: W1 [K,N] fp32 -> W1^T [N,K] bf16 (tiled transpose)
__global__ __launch_bounds__(256) void convert_Wt(const float* __restrict__ W1)
{
    __shared__ float t[32][33];
    const int n0 = blockIdx.x * 32, k0 = blockIdx.y * 32;
    const int tx = threadIdx.x & 31, ty = threadIdx.x >> 5;   // 32 x 8
#pragma unroll
    for (int i = 0; i < 4; i++)
        t[ty + 8 * i][tx] = W1[(size_t)(k0 + ty + 8 * i) * ATTH + n0 + tx];
    __syncthreads();
#pragma unroll
    for (int i = 0; i < 4; i++)
        g_Wt[(size_t)(n0 + ty + 8 * i) * HID + k0 + tx] = __float2bfloat16_rn(t[tx][ty + 8 * i]);
}

// ---------------------------------------------------------------------------
// bf16 split-precision GEMM via mma.sync + fused epilogue.
// grid (256, 8), 256 threads. CTA tile M128 x N128, K-tile 64, double buffered.
// ---------------------------------------------------------------------------
#define OFF_AHI 0
#define OFF_ALO 16384
#define OFF_B   32768
#define BUFB    49152
#define SMEM_GEMM (2*BUFB)

__global__ __launch_bounds__(256, 2) void score_gemm_mma(
    const float* __restrict__ b1, const float* __restrict__ W2)
{
    extern __shared__ __align__(128) char smem[];
    const uint32_t sb = smem_u32(smem);
    const int bm = blockIdx.x, bn = blockIdx.y;
    const int tid = threadIdx.x;
    const int lane = tid & 31, wid = tid >> 5;
    const int wid_m = wid >> 2, wid_n = wid & 3;

    const __nv_bfloat16* Ah = g_Xhi + (size_t)(bm * BM) * HID;
    const __nv_bfloat16* Al = g_Xlo + (size_t)(bm * BM) * HID;
    const __nv_bfloat16* Bt = g_Wt  + (size_t)(bn * BN) * HID;

    float acc[4][4][4];
#pragma unroll
    for (int i = 0; i < 4; i++)
#pragma unroll
        for (int j = 0; j < 4; j++)
#pragma unroll
            for (int q = 0; q < 4; q++) acc[i][j][q] = 0.f;

    // loader lambda: issue 12 cp.async for ktile kt into buffer buf
    auto issue = [&](int kt, int buf) {
        const uint32_t bufb = sb + buf * BUFB;
#pragma unroll
        for (int j = 0; j < 4; j++) {
            int id = tid + 256 * j;          // 0..1023
            int r = id >> 3, c8 = id & 7;
            uint32_t o = (uint32_t)(r * 128 + c8 * 16);
            o ^= (uint32_t)((r & 7) << 4);
            const char* srcA = (const char*)(Ah + (size_t)r * HID + kt * BK) + c8 * 16;
            const char* srcL = (const char*)(Al + (size_t)r * HID + kt * BK) + c8 * 16;
            const char* srcB = (const char*)(Bt + (size_t)r * HID + kt * BK) + c8 * 16;
            cp16(bufb + OFF_AHI + o, srcA);
            cp16(bufb + OFF_ALO + o, srcL);
            cp16(bufb + OFF_B   + o, srcB);
        }
        CP_COMMIT();
    };

    issue(0, 0);

    for (int kt = 0; kt < NKT; kt++) {
        if (kt + 1 < NKT) {
            issue(kt + 1, (kt + 1) & 1);
            CP_WAIT(1);
        } else {
            CP_WAIT(0);
        }
        __syncthreads();

        const uint32_t bufb = sb + (kt & 1) * BUFB;
#pragma unroll
        for (int ks = 0; ks < 4; ks++) {
            const int rrow = lane & 15;
            const int bc = ks * 32 + ((lane >> 4) << 4);
            uint32_t a_hi[4][4], a_lo[4][4], bq[2][4];
#pragma unroll
            for (int mi = 0; mi < 4; mi++) {
                int ra = wid_m * 64 + mi * 16 + rrow;
                uint32_t o = (uint32_t)(ra * 128 + bc) ^ (uint32_t)((ra & 7) << 4);
                ldm_x4(a_hi[mi], bufb + OFF_AHI + o);
                ldm_x4(a_lo[mi], bufb + OFF_ALO + o);
            }
#pragma unroll
            for (int nb = 0; nb < 2; nb++) {
                int rb = wid_n * 32 + nb * 16 + rrow;
                uint32_t o = (uint32_t)(rb * 128 + bc) ^ (uint32_t)((rb & 7) << 4);
                ldm_x4(bq[nb], bufb + OFF_B + o);
            }
#pragma unroll
            for (int mi = 0; mi < 4; mi++) {
#pragma unroll
                for (int ni = 0; ni < 4; ni++) {
                    int nb = ni >> 1, hf = ni & 1;
                    uint32_t b0 = bq[nb][hf ? 1 : 0];
                    uint32_t b1r = bq[nb][hf ? 3 : 2];
                    mma_bf16(acc[mi][ni], a_hi[mi], b0, b1r);
                    mma_bf16(acc[mi][ni], a_lo[mi], b0, b1r);
                }
            }
        }
        __syncthreads();
    }

    // ---- fused epilogue: tanh(C + b1)*W2, reduce over 128 cols ----
    float bb[4][2], ww[4][2];
#pragma unroll
    for (int ni = 0; ni < 4; ni++) {
        int n = bn * BN + wid_n * 32 + ni * 8 + (lane & 3) * 2;
        bb[ni][0] = b1[n]; bb[ni][1] = b1[n + 1];
        ww[ni][0] = W2[n]; ww[ni][1] = W2[n + 1];
    }
    float* red = (float*)smem;   // [128][4]
#pragma unroll
    for (int mi = 0; mi < 4; mi++) {
        float s0 = 0.f, s1 = 0.f;
#pragma unroll
        for (int ni = 0; ni < 4; ni++) {
            s0 += tanh_hw(acc[mi][ni][0] + bb[ni][0]) * ww[ni][0]
                + tanh_hw(acc[mi][ni][1] + bb[ni][1]) * ww[ni][1];
            s1 += tanh_hw(acc[mi][ni][2] + bb[ni][0]) * ww[ni][0]
                + tanh_hw(acc[mi][ni][3] + bb[ni][1]) * ww[ni][1];
        }
        s0 += __shfl_xor_sync(0xffffffffu, s0, 1);
        s0 += __shfl_xor_sync(0xffffffffu, s0, 2);
        s1 += __shfl_xor_sync(0xffffffffu, s1, 1);
        s1 += __shfl_xor_sync(0xffffffffu, s1, 2);
        if ((lane & 3) == 0) {
            int r0 = wid_m * 64 + mi * 16 + (lane >> 2);
            red[(r0)     * 4 + wid_n] = s0;
            red[(r0 + 8) * 4 + wid_n] = s1;
        }
    }
    __syncthreads();
    if (tid < BM) {
        float s = (red[tid * 4 + 0] + red[tid * 4 + 1])
                + (red[tid * 4 + 2] + red[tid * 4 + 3]);
        g_part[(size_t)(bm * BM + tid) * NPART + bn] = s;
    }
}

// ---------------------------------------------------------------------------
__global__ void finalize_scores_kernel(const float* __restrict__ b2)
{
    int m = blockIdx.x * blockDim.x + threadIdx.x;
    if (m >= MTOK) return;
    const float4* p = reinterpret_cast<const float4*>(&g_part[(size_t)m * NPART]);
    float4 v0 = p[0], v1 = p[1];
    float s = ((v0.x + v0.y) + (v0.z + v0.w))
            + ((v1.x + v1.y) + (v1.z + v1.w));
    g_scores[m] = s + b2[0];
}

// ---------------------------------------------------------------------------
// Per-(batch,line) segment softmax + weighted token sum (deterministic).
// ---------------------------------------------------------------------------
__global__ __launch_bounds__(256) void aggregate_kernel(
    const float* __restrict__ X,
    const int*   __restrict__ line_ids,
    float* __restrict__ out_feats,
    float* __restrict__ out_mask,
    int write_mask)
{
    const int l = blockIdx.x;
    const int b = blockIdx.y;
    const int tid = threadIdx.x;
    const int base = b * SEQ;
    const size_t orow = (size_t)(b * LINES + l) * HID;

    __shared__ float smax[256];
    __shared__ float ssum[256];
    __shared__ int   scnt[256];
    __shared__ int   idxs[SEQ];
    __shared__ float wts[SEQ];
    __shared__ float sm_bcast, sdenom;

    float m = -INFINITY;
    for (int s = tid; s < SEQ; s += 256)
        if (line_ids[base + s] == l) m = fmaxf(m, g_scores[base + s]);
    smax[tid] = m;
    __syncthreads();
#pragma unroll
    for (int off = 128; off > 0; off >>= 1) {
        if (tid < off) smax[tid] = fmaxf(smax[tid], smax[tid + off]);
        __syncthreads();
    }
    if (tid == 0) sm_bcast = smax[0];
    __syncthreads();
    m = sm_bcast;

    if (m < -1e37f) {
        for (int c = tid; c < HID; c += 256) out_feats[orow + c] = 0.f;
        if (tid == 0 && write_mask) out_mask[b * LINES + l] = 0.f;
        return;
    }

    float lsum = 0.f; int lcnt = 0;
    for (int s = tid; s < SEQ; s += 256) {
        if (line_ids[base + s] == l) { lsum += expf(g_scores[base + s] - m); lcnt++; }
    }
    ssum[tid] = lsum; scnt[tid] = lcnt;
    __syncthreads();
#pragma unroll
    for (int off = 128; off > 0; off >>= 1) {
        if (tid < off) ssum[tid] += ssum[tid + off];
        __syncthreads();
    }
    if (tid == 0) sdenom = fmaxf(ssum[0], 1e-20f);
    __syncthreads();
    const float denom = sdenom;

    for (int off = 1; off < 256; off <<= 1) {
        int v = scnt[tid];
        int add = (tid >= off) ? scnt[tid - off] : 0;
        __syncthreads();
        scnt[tid] = v + add;
        __syncthreads();
    }
    const int cnt = scnt[255];
    int o = scnt[tid] - lcnt;

    for (int s = tid; s < SEQ; s += 256) {
        if (line_ids[base + s] == l) {
            idxs[o] = s;
            wts[o]  = expf(g_scores[base + s] - m) / denom;
            o++;
        }
    }
    __syncthreads();

    float a0 = 0.f, a1 = 0.f, a2 = 0.f;
    const float* Xb = X + (size_t)base * HID;
    for (int t = 0; t < cnt; t++) {
        const float* row = Xb + (size_t)idxs[t] * HID;
        float w = wts[t];
        a0 += w * row[tid];
        a1 += w * row[tid + 256];
        a2 += w * row[tid + 512];
    }
    out_feats[orow + tid]       = a0;
    out_feats[orow + tid + 256] = a1;
    out_feats[orow + tid + 512] = a2;
    if (tid == 0 && write_mask) out_mask[b * LINES + l] = 1.0f;
}

// ---------------------------------------------------------------------------
extern "C" void kernel_launch(void* const* d_in, const int* in_sizes, int n_in,
                              void* d_out, int out_size)
{
    const float* token_hidden = (const float*)d_in[0];
    const int*   line_ids     = (const int*)  d_in[1];
    const float* W1           = (const float*)d_in[2];
    const float* b1           = (const float*)d_in[3];
    const float* W2           = (const float*)d_in[4];
    const float* b2           = (const float*)d_in[5];

    float* out = (float*)d_out;
    const int feat_elems = BATCH * LINES * HID;
    const int mask_elems = BATCH * LINES;
    int write_mask = (out_size >= feat_elems + mask_elems) ? 1 : 0;
    float* mask_out = write_mask ? (out + feat_elems) : nullptr;

    static int smem_set = 0;
    if (!smem_set) {
        cudaFuncSetAttribute(score_gemm_mma, cudaFuncAttributeMaxDynamicSharedMemorySize, SMEM_GEMM);
        smem_set = 1;
    }

    convert_X<<<(MTOK * HID / 4) / 256, 256>>>(token_hidden);
    convert_Wt<<<dim3(ATTH / 32, HID / 32), 256>>>(W1);

    score_gemm_mma<<<dim3(MTOK / BM, ATTH / BN), 256, SMEM_GEMM>>>(b1, W2);

    finalize_scores_kernel<<<MTOK / 256, 256>>>(b2);

    aggregate_kernel<<<dim3(LINES, BATCH), 256>>>(token_hidden, line_ids, out, mask_out, write_mask);
}

// round 5
// speedup vs baseline: 4.3199x; 1.0270x over previous
#include <cuda_runtime.h>
#include <cuda_fp16.h>
#include <math.h>
#include <stdint.h>

// Problem constants
#define BATCH   8
#define SEQ     4096
#define HID     768
#define LINES   256
#define ATTH    1024
#define MTOK    (BATCH*SEQ)      // 32768
#define NPART   4                // 4 N-tiles of 256

#define BM 128
#define BN 256
#define BK 64
#define NKT (HID/BK)             // 12

// ---- scratch (static device globals) ----
__device__ __half g_Xhi[(size_t)MTOK * HID];
__device__ __half g_Xlo[(size_t)MTOK * HID];
__device__ __half g_Wt [(size_t)ATTH * HID];   // W1^T [N][K]
__device__ float g_part[MTOK * NPART];
__device__ float g_scores[MTOK];

__device__ __forceinline__ float tanh_hw(float x) {
    float y; asm("tanh.approx.f32 %0, %1;" : "=f"(y) : "f"(x)); return y;
}
__device__ __forceinline__ uint32_t smem_u32(const void* p) {
    uint32_t a;
    asm("{ .reg .u64 t; cvta.to.shared.u64 t, %1; cvt.u32.u64 %0, t; }" : "=r"(a) : "l"(p));
    return a;
}
__device__ __forceinline__ void cp16(uint32_t dst, const void* src) {
    asm volatile("cp.async.cg.shared.global [%0], [%1], 16;" :: "r"(dst), "l"(src) : "memory");
}
#define CP_COMMIT()  asm volatile("cp.async.commit_group;" ::: "memory")
#define CP_WAIT(n)   asm volatile("cp.async.wait_group %0;" :: "n"(n) : "memory")

__device__ __forceinline__ void ldm_x4(uint32_t* r, uint32_t addr) {
    asm volatile("ldmatrix.sync.aligned.m8n8.x4.shared.b16 {%0,%1,%2,%3}, [%4];"
                 : "=r"(r[0]), "=r"(r[1]), "=r"(r[2]), "=r"(r[3]) : "r"(addr));
}
__device__ __forceinline__ void mma_f16(float* c, const uint32_t* a, uint32_t b0, uint32_t b1) {
    asm volatile("mma.sync.aligned.m16n8k16.row.col.f32.f16.f16.f32 "
                 "{%0,%1,%2,%3}, {%4,%5,%6,%7}, {%8,%9}, {%0,%1,%2,%3};"
                 : "+f"(c[0]), "+f"(c[1]), "+f"(c[2]), "+f"(c[3])
                 : "r"(a[0]), "r"(a[1]), "r"(a[2]), "r"(a[3]), "r"(b0), "r"(b1));
}

// ---------------------------------------------------------------------------
// Conversion: X fp32 -> hi/lo fp16 planes (row-major)
// ---------------------------------------------------------------------------
__global__ __launch_bounds__(256) void convert_X(const float* __restrict__ X)
{
    size_t i4 = (size_t)blockIdx.x * 256 + threadIdx.x;   // float4 index
    float4 v = reinterpret_cast<const float4*>(X)[i4];
    float xs[4] = {v.x, v.y, v.z, v.w};
    __half h[4], l[4];
#pragma unroll
    for (int i = 0; i < 4; i++) {
        h[i] = __float2half_rn(xs[i]);
        l[i] = __float2half_rn(xs[i] - __half2float(h[i]));
    }
    reinterpret_cast<uint2*>(g_Xhi)[i4] = *reinterpret_cast<uint2*>(h);
    reinterpret_cast<uint2*>(g_Xlo)[i4] = *reinterpret_cast<uint2*>(l);
}

// Conversion: W1 [K,N] fp32 -> W1^T [N,K] fp16 (tiled transpose)
__global__ __launch_bounds__(256) void convert_Wt(const float* __restrict__ W1)
{
    __shared__ float t[32][33];
    const int n0 = blockIdx.x * 32, k0 = blockIdx.y * 32;
    const int tx = threadIdx.x & 31, ty = threadIdx.x >> 5;   // 32 x 8
#pragma unroll
    for (int i = 0; i < 4; i++)
        t[ty + 8 * i][tx] = W1[(size_t)(k0 + ty + 8 * i) * ATTH + n0 + tx];
    __syncthreads();
#pragma unroll
    for (int i = 0; i < 4; i++)
        g_Wt[(size_t)(n0 + ty + 8 * i) * HID + k0 + tx] = __float2half_rn(t[tx][ty + 8 * i]);
}

// ---------------------------------------------------------------------------
// fp16 split-precision GEMM via mma.sync + fused epilogue.
// grid (4, 256) — bn fastest for L2 reuse of A. 256 threads.
// CTA tile M128 x N256, warp tile 64x64 (8 warps, 2m x 4n), K-tile 64.
// ---------------------------------------------------------------------------
#define OFF_AHI 0
#define OFF_ALO 16384
#define OFF_B   32768
#define BUFB    65536
#define SMEM_GEMM (2*BUFB)       // 131072

__global__ __launch_bounds__(256, 1) void score_gemm_mma(
    const float* __restrict__ b1, const float* __restrict__ W2)
{
    extern __shared__ __align__(128) char smem[];
    const uint32_t sb = smem_u32(smem);
    const int bn = blockIdx.x, bm = blockIdx.y;
    const int tid = threadIdx.x;
    const int lane = tid & 31, wid = tid >> 5;
    const int wid_m = wid >> 2, wid_n = wid & 3;

    const __half* Ah = g_Xhi + (size_t)(bm * BM) * HID;
    const __half* Al = g_Xlo + (size_t)(bm * BM) * HID;
    const __half* Bt = g_Wt  + (size_t)(bn * BN) * HID;

    float acc[4][8][4];
#pragma unroll
    for (int i = 0; i < 4; i++)
#pragma unroll
        for (int j = 0; j < 8; j++)
#pragma unroll
            for (int q = 0; q < 4; q++) acc[i][j][q] = 0.f;

    auto issue = [&](int kt, int buf) {
        const uint32_t bufb = sb + buf * BUFB;
#pragma unroll
        for (int j = 0; j < 4; j++) {              // A hi+lo: 128 rows x 8 chunks
            int id = tid + 256 * j;
            int r = id >> 3, c8 = id & 7;
            uint32_t o = (uint32_t)(r * 128 + c8 * 16) ^ (uint32_t)((r & 7) << 4);
            const char* pA = (const char*)(Ah + (size_t)r * HID + kt * BK) + c8 * 16;
            const char* pL = (const char*)(Al + (size_t)r * HID + kt * BK) + c8 * 16;
            cp16(bufb + OFF_AHI + o, pA);
            cp16(bufb + OFF_ALO + o, pL);
        }
#pragma unroll
        for (int j = 0; j < 8; j++) {              // B: 256 rows x 8 chunks
            int id = tid + 256 * j;
            int r = id >> 3, c8 = id & 7;
            uint32_t o = (uint32_t)(r * 128 + c8 * 16) ^ (uint32_t)((r & 7) << 4);
            const char* pB = (const char*)(Bt + (size_t)r * HID + kt * BK) + c8 * 16;
            cp16(bufb + OFF_B + o, pB);
        }
        CP_COMMIT();
    };

    issue(0, 0);

    for (int kt = 0; kt < NKT; kt++) {
        if (kt + 1 < NKT) { issue(kt + 1, (kt + 1) & 1); CP_WAIT(1); }
        else             { CP_WAIT(0); }
        __syncthreads();

        const uint32_t bufb = sb + (kt & 1) * BUFB;
        const int rrow = lane & 15;
#pragma unroll
        for (int ks = 0; ks < 4; ks++) {
            const int bc = ks * 32 + ((lane >> 4) << 4);
            uint32_t ah[4][4], al[4][4], bq[4][4];
#pragma unroll
            for (int mi = 0; mi < 4; mi++) {
                int ra = wid_m * 64 + mi * 16 + rrow;
                uint32_t o = (uint32_t)(ra * 128 + bc) ^ (uint32_t)((ra & 7) << 4);
                ldm_x4(ah[mi], bufb + OFF_AHI + o);
                ldm_x4(al[mi], bufb + OFF_ALO + o);
            }
#pragma unroll
            for (int g = 0; g < 4; g++) {
                int rb = wid_n * 64 + g * 16 + rrow;
                uint32_t o = (uint32_t)(rb * 128 + bc) ^ (uint32_t)((rb & 7) << 4);
                ldm_x4(bq[g], bufb + OFF_B + o);
            }
#pragma unroll
            for (int mi = 0; mi < 4; mi++) {
#pragma unroll
                for (int ni = 0; ni < 8; ni++) {
                    int g = ni >> 1, hf = ni & 1;
                    uint32_t b0 = bq[g][hf];
                    uint32_t b1r = bq[g][hf + 2];
                    mma_f16(acc[mi][ni], ah[mi], b0, b1r);
                    mma_f16(acc[mi][ni], al[mi], b0, b1r);
                }
            }
        }
        __syncthreads();
    }

    // ---- fused epilogue: tanh(C + b1)*W2, reduce over 256 cols ----
    float bb[8][2], ww[8][2];
#pragma unroll
    for (int ni = 0; ni < 8; ni++) {
        int n = bn * BN + wid_n * 64 + ni * 8 + (lane & 3) * 2;
        bb[ni][0] = b1[n]; bb[ni][1] = b1[n + 1];
        ww[ni][0] = W2[n]; ww[ni][1] = W2[n + 1];
    }
    __syncthreads();
    float* red = (float*)smem;   // [128][4]
#pragma unroll
    for (int mi = 0; mi < 4; mi++) {
        float s0 = 0.f, s1 = 0.f;
#pragma unroll
        for (int ni = 0; ni < 8; ni++) {
            s0 += tanh_hw(acc[mi][ni][0] + bb[ni][0]) * ww[ni][0]
                + tanh_hw(acc[mi][ni][1] + bb[ni][1]) * ww[ni][1];
            s1 += tanh_hw(acc[mi][ni][2] + bb[ni][0]) * ww[ni][0]
                + tanh_hw(acc[mi][ni][3] + bb[ni][1]) * ww[ni][1];
        }
        s0 += __shfl_xor_sync(0xffffffffu, s0, 1);
        s0 += __shfl_xor_sync(0xffffffffu, s0, 2);
        s1 += __shfl_xor_sync(0xffffffffu, s1, 1);
        s1 += __shfl_xor_sync(0xffffffffu, s1, 2);
        if ((lane & 3) == 0) {
            int r0 = wid_m * 64 + mi * 16 + (lane >> 2);
            red[(r0)     * 4 + wid_n] = s0;
            red[(r0 + 8) * 4 + wid_n] = s1;
        }
    }
    __syncthreads();
    if (tid < BM) {
        float s = (red[tid * 4 + 0] + red[tid * 4 + 1])
                + (red[tid * 4 + 2] + red[tid * 4 + 3]);
        g_part[(size_t)(bm * BM + tid) * NPART + bn] = s;
    }
}

// ---------------------------------------------------------------------------
__global__ void finalize_scores_kernel(const float* __restrict__ b2)
{
    int m = blockIdx.x * blockDim.x + threadIdx.x;
    if (m >= MTOK) return;
    float4 v = reinterpret_cast<const float4*>(&g_part[(size_t)m * NPART])[0];
    g_scores[m] = ((v.x + v.y) + (v.z + v.w)) + b2[0];
}

// ---------------------------------------------------------------------------
// Per-(batch,line) segment softmax + weighted token sum (deterministic).
// 2-scan version: scores are bounded (|s| <= ||W2||_1 ~ 16) so raw exp is
// safe; exp(s)/sum(exp(s)) == exp(s-m)/sum(exp(s-m)) algebraically.
// ---------------------------------------------------------------------------
__global__ __launch_bounds__(256) void aggregate_kernel(
    const float* __restrict__ X,
    const int*   __restrict__ line_ids,
    float* __restrict__ out_feats,
    float* __restrict__ out_mask,
    int write_mask)
{
    const int l = blockIdx.x;
    const int b = blockIdx.y;
    const int tid = threadIdx.x;
    const int base = b * SEQ;
    const size_t orow = (size_t)(b * LINES + l) * HID;

    __shared__ float ssum[256];
    __shared__ int   scnt[256];
    __shared__ int   idxs[SEQ];
    __shared__ float wts[SEQ];
    __shared__ float sdenom;

    // scan 1: exp-sum and match count
    float lsum = 0.f; int lcnt = 0;
    for (int s = tid; s < SEQ; s += 256) {
        if (line_ids[base + s] == l) { lsum += expf(g_scores[base + s]); lcnt++; }
    }
    ssum[tid] = lsum; scnt[tid] = lcnt;
    __syncthreads();
#pragma unroll
    for (int off = 128; off > 0; off >>= 1) {
        if (tid < off) ssum[tid] += ssum[tid + off];
        __syncthreads();
    }
    if (tid == 0) sdenom = fmaxf(ssum[0], 1e-20f);
    __syncthreads();

    // prefix scan of counts (Hillis-Steele)
    for (int off = 1; off < 256; off <<= 1) {
        int v = scnt[tid];
        int add = (tid >= off) ? scnt[tid - off] : 0;
        __syncthreads();
        scnt[tid] = v + add;
        __syncthreads();
    }
    const int cnt = scnt[255];
    int o = scnt[tid] - lcnt;

    if (cnt == 0) {
        for (int c = tid; c < HID; c += 256) out_feats[orow + c] = 0.f;
        if (tid == 0 && write_mask) out_mask[b * LINES + l] = 0.f;
        return;
    }

    // scan 2: deterministic compaction (unnormalized weights)
    for (int s = tid; s < SEQ; s += 256) {
        if (line_ids[base + s] == l) {
            idxs[o] = s;
            wts[o]  = expf(g_scores[base + s]);
            o++;
        }
    }
    __syncthreads();

    const float inv_denom = 1.0f / sdenom;
    float a0 = 0.f, a1 = 0.f, a2 = 0.f;
    const float* Xb = X + (size_t)base * HID;
    for (int t = 0; t < cnt; t++) {
        const float* row = Xb + (size_t)idxs[t] * HID;
        float w = wts[t];
        a0 += w * row[tid];
        a1 += w * row[tid + 256];
        a2 += w * row[tid + 512];
    }
    out_feats[orow + tid]       = a0 * inv_denom;
    out_feats[orow + tid + 256] = a1 * inv_denom;
    out_feats[orow + tid + 512] = a2 * inv_denom;
    if (tid == 0 && write_mask) out_mask[b * LINES + l] = 1.0f;
}

// ---------------------------------------------------------------------------
extern "C" void kernel_launch(void* const* d_in, const int* in_sizes, int n_in,
                              void* d_out, int out_size)
{
    const float* token_hidden = (const float*)d_in[0];
    const int*   line_ids     = (const int*)  d_in[1];
    const float* W1           = (const float*)d_in[2];
    const float* b1           = (const float*)d_in[3];
    const float* W2           = (const float*)d_in[4];
    const float* b2           = (const float*)d_in[5];

    float* out = (float*)d_out;
    const int feat_elems = BATCH * LINES * HID;
    const int mask_elems = BATCH * LINES;
    int write_mask = (out_size >= feat_elems + mask_elems) ? 1 : 0;
    float* mask_out = write_mask ? (out + feat_elems) : nullptr;

    static int smem_set = 0;
    if (!smem_set) {
        cudaFuncSetAttribute(score_gemm_mma, cudaFuncAttributeMaxDynamicSharedMemorySize, SMEM_GEMM);
        smem_set = 1;
    }

    convert_X<<<(MTOK * HID / 4) / 256, 256>>>(token_hidden);
    convert_Wt<<<dim3(ATTH / 32, HID / 32), 256>>>(W1);

    score_gemm_mma<<<dim3(ATTH / BN, MTOK / BM), 256, SMEM_GEMM>>>(b1, W2);

    finalize_scores_kernel<<<MTOK / 256, 256>>>(b2);

    aggregate_kernel<<<dim3(LINES, BATCH), 256>>>(token_hidden, line_ids, out, mask_out, write_mask);
}